// round 1
// baseline (speedup 1.0000x reference)
#include <cuda_runtime.h>

#define KW 512
#define NPT 2        // points per thread
#define BLK 128      // threads per block

__global__ __launch_bounds__(BLK)
void awpinn_kernel(
    const float* __restrict__ x, const float* __restrict__ y, const float* __restrict__ z,
    const float* __restrict__ wx, const float* __restrict__ bx,
    const float* __restrict__ wy, const float* __restrict__ by,
    const float* __restrict__ wz, const float* __restrict__ bz,
    const float* __restrict__ coeff, const float* __restrict__ bias,
    float* __restrict__ out, int N)
{
    // Per-k constants, packed for LDS.128 broadcast:
    // sm0 = {wx, -bx, wy, -by}
    // sm1 = {wz, -bz, c,  0 }   c = sqrt(max(wx*wy*wz,1e-12)) * coeff
    // sm2 = {wx2, -3wx2, wy2, -3wy2}
    // sm3 = {wz2, -3wz2, 0, 0}
    __shared__ float4 sm0[KW], sm1[KW], sm2[KW], sm3[KW];

    for (int k = threadIdx.x; k < KW; k += BLK) {
        float wxk = wx[k], wyk = wy[k], wzk = wz[k];
        float c   = sqrtf(fmaxf(wxk * wyk * wzk, 1e-12f)) * coeff[k];
        float wx2 = wxk * wxk, wy2 = wyk * wyk, wz2 = wzk * wzk;
        sm0[k] = make_float4(wxk, -bx[k], wyk, -by[k]);
        sm1[k] = make_float4(wzk, -bz[k], c, 0.0f);
        sm2[k] = make_float4(wx2, -3.0f * wx2, wy2, -3.0f * wy2);
        sm3[k] = make_float4(wz2, -3.0f * wz2, 0.0f, 0.0f);
    }
    __syncthreads();

    const int p0 = blockIdx.x * (BLK * NPT) + threadIdx.x;

    float xv[NPT], yv[NPT], zv[NPT];
    float a0[NPT], axx[NPT], ayy[NPT], azz[NPT];

    #pragma unroll
    for (int i = 0; i < NPT; i++) {
        int n = p0 + i * BLK;
        bool ok = (n < N);
        xv[i] = ok ? x[n] : 0.0f;
        yv[i] = ok ? y[n] : 0.0f;
        zv[i] = ok ? z[n] : 0.0f;
        a0[i] = 0.0f; axx[i] = 0.0f; ayy[i] = 0.0f; azz[i] = 0.0f;
    }

    // exp(-0.5*t) = 2^(t * -0.5*log2(e)) = ex2(t * -0.72134752f)
    const float NEG_HALF_LOG2E = -0.7213475204444817f;

    #pragma unroll 2
    for (int k = 0; k < KW; k++) {
        float4 s0 = sm0[k];
        float4 s1 = sm1[k];
        float4 s2 = sm2[k];
        float4 s3 = sm3[k];

        #pragma unroll
        for (int i = 0; i < NPT; i++) {
            float xt = fmaf(xv[i], s0.x, s0.y);
            float yt = fmaf(yv[i], s0.z, s0.w);
            float zt = fmaf(zv[i], s1.x, s1.y);

            float x2 = xt * xt;
            float y2 = yt * yt;
            float z2 = zt * zt;

            float ex, ey, ez;
            asm("ex2.approx.ftz.f32 %0, %1;" : "=f"(ex) : "f"(x2 * NEG_HALF_LOG2E));
            asm("ex2.approx.ftz.f32 %0, %1;" : "=f"(ey) : "f"(y2 * NEG_HALF_LOG2E));
            asm("ex2.approx.ftz.f32 %0, %1;" : "=f"(ez) : "f"(z2 * NEG_HALF_LOG2E));

            float gx = -xt * ex;   // xw
            float gy = -yt * ey;   // yw
            float gz = -zt * ez;   // zw

            float P  = (gx * gy) * gz;
            float cp = s1.z * P;

            a0[i] += cp;
            axx[i] = fmaf(cp, fmaf(s2.x, x2, s2.y), axx[i]);
            ayy[i] = fmaf(cp, fmaf(s2.z, y2, s2.w), ayy[i]);
            azz[i] = fmaf(cp, fmaf(s3.x, z2, s3.y), azz[i]);
        }
    }

    float b = bias[0];
    #pragma unroll
    for (int i = 0; i < NPT; i++) {
        int n = p0 + i * BLK;
        if (n < N) {
            out[n]         = a0[i] + b;
            out[N + n]     = axx[i];
            out[2 * N + n] = ayy[i];
            out[3 * N + n] = azz[i];
        }
    }
}

extern "C" void kernel_launch(void* const* d_in, const int* in_sizes, int n_in,
                              void* d_out, int out_size)
{
    const float* x     = (const float*)d_in[0];
    const float* y     = (const float*)d_in[1];
    const float* z     = (const float*)d_in[2];
    const float* wx    = (const float*)d_in[3];
    const float* bx    = (const float*)d_in[4];
    const float* wy    = (const float*)d_in[5];
    const float* by    = (const float*)d_in[6];
    const float* wz    = (const float*)d_in[7];
    const float* bz    = (const float*)d_in[8];
    const float* coeff = (const float*)d_in[9];
    const float* bias  = (const float*)d_in[10];
    float* out = (float*)d_out;

    int N = in_sizes[0];
    int pts_per_block = BLK * NPT;
    int grid = (N + pts_per_block - 1) / pts_per_block;

    awpinn_kernel<<<grid, BLK>>>(x, y, z, wx, bx, wy, by, wz, bz, coeff, bias, out, N);
}

// round 2
// speedup vs baseline: 1.2755x; 1.2755x over previous
#include <cuda_runtime.h>

#define KW   512
#define KP   (KW / 2)   // k-pairs
#define NPT  2          // points per thread
#define BLK  128        // threads per block

// ---------- packed f32x2 helpers ----------
__device__ __forceinline__ unsigned long long pk2(float lo, float hi) {
    unsigned long long r;
    asm("mov.b64 %0, {%1, %2};" : "=l"(r) : "f"(lo), "f"(hi));
    return r;
}
__device__ __forceinline__ void upk2(unsigned long long v, float& lo, float& hi) {
    asm("mov.b64 {%0, %1}, %2;" : "=f"(lo), "=f"(hi) : "l"(v));
}
__device__ __forceinline__ unsigned long long fma2(unsigned long long a,
                                                   unsigned long long b,
                                                   unsigned long long c) {
    unsigned long long d;
    asm("fma.rn.f32x2 %0, %1, %2, %3;" : "=l"(d) : "l"(a), "l"(b), "l"(c));
    return d;
}
__device__ __forceinline__ unsigned long long mul2(unsigned long long a,
                                                   unsigned long long b) {
    unsigned long long d;
    asm("mul.rn.f32x2 %0, %1, %2;" : "=l"(d) : "l"(a), "l"(b));
    return d;
}
__device__ __forceinline__ unsigned long long add2(unsigned long long a,
                                                   unsigned long long b) {
    unsigned long long d;
    asm("add.rn.f32x2 %0, %1, %2;" : "=l"(d) : "l"(a), "l"(b));
    return d;
}
__device__ __forceinline__ float ex2f(float a) {
    float r;
    asm("ex2.approx.ftz.f32 %0, %1;" : "=f"(r) : "f"(a));
    return r;
}

// Per k-pair constants: 7 float4, each float4 = two packed f32x2 lanes:
//  v0 = {wx0,wx1,  -bx0,-bx1}
//  v1 = {wy0,wy1,  -by0,-by1}
//  v2 = {wz0,wz1,  -bz0,-bz1}
//  v3 = {-c0,-c1,  wx2_0,wx2_1}          c = sqrt(max(wx*wy*wz,1e-12))*coeff
//  v4 = {-3wx2,    wy2}
//  v5 = {-3wy2,    wz2}
//  v6 = {-3wz2,    pad}
__global__ __launch_bounds__(BLK)
void awpinn_kernel(
    const float* __restrict__ x, const float* __restrict__ y, const float* __restrict__ z,
    const float* __restrict__ wx, const float* __restrict__ bx,
    const float* __restrict__ wy, const float* __restrict__ by,
    const float* __restrict__ wz, const float* __restrict__ bz,
    const float* __restrict__ coeff, const float* __restrict__ bias,
    float* __restrict__ out, int N)
{
    __shared__ float4 kc[KP][7];

    for (int kp = threadIdx.x; kp < KP; kp += BLK) {
        int k0 = 2 * kp, k1 = k0 + 1;
        float wx0 = wx[k0], wx1 = wx[k1];
        float wy0 = wy[k0], wy1 = wy[k1];
        float wz0 = wz[k0], wz1 = wz[k1];
        float c0 = sqrtf(fmaxf(wx0 * wy0 * wz0, 1e-12f)) * coeff[k0];
        float c1 = sqrtf(fmaxf(wx1 * wy1 * wz1, 1e-12f)) * coeff[k1];
        float wx20 = wx0 * wx0, wx21 = wx1 * wx1;
        float wy20 = wy0 * wy0, wy21 = wy1 * wy1;
        float wz20 = wz0 * wz0, wz21 = wz1 * wz1;
        kc[kp][0] = make_float4(wx0, wx1, -bx[k0], -bx[k1]);
        kc[kp][1] = make_float4(wy0, wy1, -by[k0], -by[k1]);
        kc[kp][2] = make_float4(wz0, wz1, -bz[k0], -bz[k1]);
        kc[kp][3] = make_float4(-c0, -c1, wx20, wx21);
        kc[kp][4] = make_float4(-3.0f * wx20, -3.0f * wx21, wy20, wy21);
        kc[kp][5] = make_float4(-3.0f * wy20, -3.0f * wy21, wz20, wz21);
        kc[kp][6] = make_float4(-3.0f * wz20, -3.0f * wz21, 0.0f, 0.0f);
    }
    __syncthreads();

    const int p0 = blockIdx.x * (BLK * NPT) + threadIdx.x;

    unsigned long long xd[NPT], yd[NPT], zd[NPT];
    unsigned long long a0[NPT], axx[NPT], ayy[NPT], azz[NPT];

    #pragma unroll
    for (int i = 0; i < NPT; i++) {
        int n = p0 + i * BLK;
        bool ok = (n < N);
        float xv = ok ? x[n] : 0.0f;
        float yv = ok ? y[n] : 0.0f;
        float zv = ok ? z[n] : 0.0f;
        xd[i] = pk2(xv, xv);
        yd[i] = pk2(yv, yv);
        zd[i] = pk2(zv, zv);
        a0[i] = 0ull; axx[i] = 0ull; ayy[i] = 0ull; azz[i] = 0ull;
    }

    // exp(-0.5*s) = ex2(s * -0.5*log2(e))
    const float NEG_HALF_LOG2E = -0.7213475204444817f;
    const unsigned long long Cd = pk2(NEG_HALF_LOG2E, NEG_HALF_LOG2E);

    #pragma unroll 2
    for (int kp = 0; kp < KP; kp++) {
        // load 7 float4 -> 14 packed f32x2 constants
        const float4 v0 = kc[kp][0];
        const float4 v1 = kc[kp][1];
        const float4 v2 = kc[kp][2];
        const float4 v3 = kc[kp][3];
        const float4 v4 = kc[kp][4];
        const float4 v5 = kc[kp][5];
        const float4 v6 = kc[kp][6];

        unsigned long long wxp  = pk2(v0.x, v0.y), mbx = pk2(v0.z, v0.w);
        unsigned long long wyp  = pk2(v1.x, v1.y), mby = pk2(v1.z, v1.w);
        unsigned long long wzp  = pk2(v2.x, v2.y), mbz = pk2(v2.z, v2.w);
        unsigned long long cneg = pk2(v3.x, v3.y), wx2 = pk2(v3.z, v3.w);
        unsigned long long m3wx2= pk2(v4.x, v4.y), wy2 = pk2(v4.z, v4.w);
        unsigned long long m3wy2= pk2(v5.x, v5.y), wz2 = pk2(v5.z, v5.w);
        unsigned long long m3wz2= pk2(v6.x, v6.y);

        #pragma unroll
        for (int i = 0; i < NPT; i++) {
            unsigned long long xt = fma2(xd[i], wxp, mbx);
            unsigned long long yt = fma2(yd[i], wyp, mby);
            unsigned long long zt = fma2(zd[i], wzp, mbz);

            unsigned long long x2 = mul2(xt, xt);
            unsigned long long y2 = mul2(yt, yt);
            unsigned long long z2 = mul2(zt, zt);

            unsigned long long s  = add2(add2(x2, y2), z2);
            unsigned long long arg = mul2(s, Cd);

            float alo, ahi;
            upk2(arg, alo, ahi);
            unsigned long long e = pk2(ex2f(alo), ex2f(ahi));

            // P = -(xt*yt*zt)*e ;  cp = c*P = cneg*(xt*yt*zt*e)
            unsigned long long q  = mul2(mul2(xt, yt), zt);
            unsigned long long pe = mul2(q, e);
            unsigned long long cp = mul2(cneg, pe);

            a0[i] = add2(a0[i], cp);
            axx[i] = fma2(cp, fma2(wx2, x2, m3wx2), axx[i]);
            ayy[i] = fma2(cp, fma2(wy2, y2, m3wy2), ayy[i]);
            azz[i] = fma2(cp, fma2(wz2, z2, m3wz2), azz[i]);
        }
    }

    float b = bias[0];
    #pragma unroll
    for (int i = 0; i < NPT; i++) {
        int n = p0 + i * BLK;
        if (n < N) {
            float lo, hi;
            upk2(a0[i], lo, hi);  out[n]         = lo + hi + b;
            upk2(axx[i], lo, hi); out[N + n]     = lo + hi;
            upk2(ayy[i], lo, hi); out[2 * N + n] = lo + hi;
            upk2(azz[i], lo, hi); out[3 * N + n] = lo + hi;
        }
    }
}

extern "C" void kernel_launch(void* const* d_in, const int* in_sizes, int n_in,
                              void* d_out, int out_size)
{
    const float* x     = (const float*)d_in[0];
    const float* y     = (const float*)d_in[1];
    const float* z     = (const float*)d_in[2];
    const float* wx    = (const float*)d_in[3];
    const float* bx    = (const float*)d_in[4];
    const float* wy    = (const float*)d_in[5];
    const float* by    = (const float*)d_in[6];
    const float* wz    = (const float*)d_in[7];
    const float* bz    = (const float*)d_in[8];
    const float* coeff = (const float*)d_in[9];
    const float* bias  = (const float*)d_in[10];
    float* out = (float*)d_out;

    int N = in_sizes[0];
    int pts_per_block = BLK * NPT;
    int grid = (N + pts_per_block - 1) / pts_per_block;

    awpinn_kernel<<<grid, BLK>>>(x, y, z, wx, bx, wy, by, wz, bz, coeff, bias, out, N);
}